// round 1
// baseline (speedup 1.0000x reference)
#include <cuda_runtime.h>
#include <math.h>

#define NLEV 16
#define RESO 2048
#define PRIME_Y 2654435761u

struct Levels {
    float    scale[NLEV];
    unsigned res[NLEV];
    unsigned size[NLEV];
    unsigned offset[NLEV];
    unsigned hashed[NLEV];
};

typedef unsigned long long u64;

__device__ __forceinline__ u64 pk2(float lo, float hi) {
    u64 r; asm("mov.b64 %0,{%1,%2};" : "=l"(r) : "f"(lo), "f"(hi)); return r;
}
__device__ __forceinline__ float2 upk2(u64 a) {
    float2 f; asm("mov.b64 {%0,%1},%2;" : "=f"(f.x), "=f"(f.y) : "l"(a)); return f;
}
__device__ __forceinline__ u64 ffma2(u64 a, u64 b, u64 c) {
    u64 d; asm("fma.rn.f32x2 %0,%1,%2,%3;" : "=l"(d) : "l"(a), "l"(b), "l"(c)); return d;
}

__device__ __forceinline__ float decode_bound(const unsigned* p, int elems) {
    if (!p || elems <= 0) return 1.0f;
    unsigned a = p[0];
    float ff = __uint_as_float(a);
    if (isfinite(ff) && fabsf(ff) > 1e-6f && fabsf(ff) < 1e9f) return ff;
    int ai = (int)a;
    if (ai != 0 && ai > -1000000000 && ai < 1000000000) return (float)ai;
    if (elems >= 2) {
        double d = __hiloint2double((int)p[1], (int)a);
        if (isfinite(d) && fabs(d) > 1e-6 && fabs(d) < 1e9) return (float)d;
    }
    return 1.0f;
}

__global__ __launch_bounds__(256)
void plane_kernel(const float2* __restrict__ xy,
                  const float2* __restrict__ table,
                  const float*  __restrict__ w0,
                  const float*  __restrict__ w1,
                  const unsigned* __restrict__ bound_raw,
                  int bound_elems,
                  float* __restrict__ out,
                  int N, Levels L)
{
    __shared__ float sW0[64 * 32];   // [j][i], row j contiguous (128B aligned rows)
    __shared__ float sW1t[64 * 8];   // transposed: [j][k]

    for (int i = threadIdx.x; i < 64 * 32; i += blockDim.x) sW0[i] = w0[i];
    for (int i = threadIdx.x; i < 64 * 8; i += blockDim.x) {
        int k = i >> 6, j = i & 63;
        sW1t[j * 8 + k] = w1[i];
    }
    __syncthreads();

    int n = blockIdx.x * blockDim.x + threadIdx.x;
    if (n >= N) return;

    float bound = decode_bound(bound_raw, bound_elems);

    float2 p = xy[n];
    float inv2b = 0.5f / bound;
    float nx = (p.x + bound) * inv2b;
    float ny = (p.y + bound) * inv2b;
    float cx = fminf(fmaxf(nx * (float)RESO - 0.5f, 0.0f), (float)(RESO - 1));
    float cy = fminf(fmaxf(ny * (float)RESO - 0.5f, 0.0f), (float)(RESO - 1));
    float cx0 = floorf(cx), cy0 = floorf(cy);
    float cx1 = fminf(cx0 + 1.0f, (float)(RESO - 1));
    float cy1 = fminf(cy0 + 1.0f, (float)(RESO - 1));
    float u = cx - cx0, v = cy - cy0;

    u64 O[4];
    #pragma unroll
    for (int k = 0; k < 4; k++) O[k] = 0ull;

    // 4 outer bilinear corners; loop kept rolled (selects instead of arrays —
    // keeps F[] in registers and I-footprint ~1x).
    #pragma unroll 1
    for (int cc = 0; cc < 4; cc++) {
        int bx = cc & 1, by = cc >> 1;
        float a  = bx ? cx1 : cx0;
        float bb = by ? cy1 : cy0;
        float cw = (bx ? u : 1.0f - u) * (by ? v : 1.0f - v);

        float gx = (a  + 0.5f) * (1.0f / (float)RESO);
        float gy = (bb + 0.5f) * (1.0f / (float)RESO);

        u64 F[NLEV];   // packed (f2l, f2l+1) per level

        #pragma unroll
        for (int l = 0; l < NLEV; l++) {
            float    scale  = L.scale[l];
            unsigned res    = L.res[l];
            unsigned size   = L.size[l];
            unsigned off    = L.offset[l];
            bool     hashed = (L.hashed[l] != 0);

            float px = fmaf(gx, scale, 0.5f);
            float py = fmaf(gy, scale, 0.5f);
            float fx = floorf(px), fy = floorf(py);
            float frx = px - fx, fry = py - fy;
            unsigned ix = (unsigned)fx, iy = (unsigned)fy;
            float wx0 = 1.0f - frx, wy0 = 1.0f - fry;

            float accx = 0.0f, accy = 0.0f;
            #pragma unroll
            for (int d = 0; d < 4; d++) {
                unsigned gxx = ix + (unsigned)(d & 1);
                unsigned gyy = iy + (unsigned)(d >> 1);
                unsigned idx;
                if (hashed) {
                    idx = (gxx ^ (gyy * PRIME_Y)) & (size - 1u);
                } else {
                    idx = gxx + gyy * res;
                    if (idx >= size) idx -= size;
                }
                float w = ((d & 1) ? frx : wx0) * ((d >> 1) ? fry : wy0);
                float2 t = __ldg(&table[off + idx]);
                accx = fmaf(w, t.x, accx);
                accy = fmaf(w, t.y, accy);
            }
            F[l] = pk2(accx, accy);
        }

        // MLP: 32 -> 64 (relu) -> 8, packed f32x2 math, weights broadcast from shared
        #pragma unroll 2
        for (int j = 0; j < 64; j++) {
            const ulonglong2* wr = (const ulonglong2*)&sW0[j * 32];
            u64 sa = 0ull, sb = 0ull;
            #pragma unroll
            for (int i = 0; i < 8; i++) {
                ulonglong2 wp = wr[i];
                sa = ffma2(F[2 * i],     wp.x, sa);
                sb = ffma2(F[2 * i + 1], wp.y, sb);
            }
            float2 av = upk2(sa), bv = upk2(sb);
            float s = (av.x + av.y) + (bv.x + bv.y);
            s = fmaxf(s, 0.0f) * cw;
            u64 t2 = pk2(s, s);
            const ulonglong2* w1p = (const ulonglong2*)&sW1t[j * 8];
            ulonglong2 wa = w1p[0], wb = w1p[1];
            O[0] = ffma2(t2, wa.x, O[0]);
            O[1] = ffma2(t2, wa.y, O[1]);
            O[2] = ffma2(t2, wb.x, O[2]);
            O[3] = ffma2(t2, wb.y, O[3]);
        }
    }

    float2 r0 = upk2(O[0]), r1 = upk2(O[1]), r2 = upk2(O[2]), r3 = upk2(O[3]);
    float4* op = (float4*)(out + (size_t)n * 8);
    op[0] = make_float4(r0.x, r0.y, r1.x, r1.y);
    op[1] = make_float4(r2.x, r2.y, r3.x, r3.y);
}

extern "C" void kernel_launch(void* const* d_in, const int* in_sizes, int n_in,
                              void* d_out, int out_size)
{
    const float2* xy    = (const float2*)d_in[0];
    const float2* table = (const float2*)d_in[1];
    const float*  w0    = (const float*)d_in[2];
    const float*  w1    = (const float*)d_in[3];
    const unsigned* bound = (n_in > 4) ? (const unsigned*)d_in[4] : nullptr;
    int bound_elems = (n_in > 4) ? in_sizes[4] : 0;

    int N = in_sizes[0] / 2;

    // Level constants — same double-precision libm sequence as the numpy reference,
    // so ceil() boundaries match exactly.
    Levels L;
    double b = exp2(log2(2048.0 / 16.0) / 15.0);
    unsigned off = 0;
    for (int l = 0; l < NLEV; l++) {
        double s = 16.0 * pow(b, (double)l) - 1.0;
        int r = (int)ceil(s) + 1;
        unsigned long long pp = (unsigned long long)r * (unsigned long long)r;
        unsigned psz = (pp > (unsigned long long)(1u << 19)) ? (1u << 19) : (unsigned)pp;
        psz = (psz + 7u) / 8u * 8u;
        L.scale[l]  = (float)s;
        L.res[l]    = (unsigned)r;
        L.size[l]   = psz;
        L.offset[l] = off;
        L.hashed[l] = (pp > (unsigned long long)psz) ? 1u : 0u;
        off += psz;
    }

    int threads = 256;
    int blocks = (N + threads - 1) / threads;
    plane_kernel<<<blocks, threads>>>(xy, table, w0, w1, bound, bound_elems,
                                      (float*)d_out, N, L);
}

// round 2
// speedup vs baseline: 1.1232x; 1.1232x over previous
#include <cuda_runtime.h>
#include <math.h>

#define NLEV 16
#define RESO 2048
#define PRIME_Y 2654435761u

struct Levels {
    float    scale[NLEV];
    unsigned res[NLEV];
    unsigned size[NLEV];
    unsigned offset[NLEV];
    unsigned hashed[NLEV];
};

typedef unsigned long long u64;

__constant__ float cW0[64 * 32];   // [j][i] row-major, as given
__constant__ float cW1[8 * 64];    // [k][j] row-major, as given

__device__ __forceinline__ u64 pk2(float lo, float hi) {
    u64 r; asm("mov.b64 %0,{%1,%2};" : "=l"(r) : "f"(lo), "f"(hi)); return r;
}
__device__ __forceinline__ float2 upk2(u64 a) {
    float2 f; asm("mov.b64 {%0,%1},%2;" : "=f"(f.x), "=f"(f.y) : "l"(a)); return f;
}
__device__ __forceinline__ u64 ffma2(u64 a, u64 b, u64 c) {
    u64 d; asm("fma.rn.f32x2 %0,%1,%2,%3;" : "=l"(d) : "l"(a), "l"(b), "l"(c)); return d;
}
__device__ __forceinline__ u64 add2(u64 a, u64 b) {
    u64 d; asm("add.rn.f32x2 %0,%1,%2;" : "=l"(d) : "l"(a), "l"(b)); return d;
}

__device__ __forceinline__ float decode_bound(const unsigned* p, int elems) {
    if (!p || elems <= 0) return 1.0f;
    unsigned a = p[0];
    float ff = __uint_as_float(a);
    if (isfinite(ff) && fabsf(ff) > 1e-6f && fabsf(ff) < 1e9f) return ff;
    int ai = (int)a;
    if (ai != 0 && ai > -1000000000 && ai < 1000000000) return (float)ai;
    if (elems >= 2) {
        double d = __hiloint2double((int)p[1], (int)a);
        if (isfinite(d) && fabs(d) > 1e-6 && fabs(d) < 1e9) return (float)d;
    }
    return 1.0f;
}

__global__ __launch_bounds__(128)
void plane_kernel(const float2* __restrict__ xy,
                  const float2* __restrict__ table,
                  const unsigned* __restrict__ bound_raw,
                  int bound_elems,
                  float* __restrict__ out,
                  int N, Levels L)
{
    int n = blockIdx.x * blockDim.x + threadIdx.x;
    if (n >= N) return;

    float bound = decode_bound(bound_raw, bound_elems);

    float2 p = xy[n];
    float inv2b = 0.5f / bound;
    float nx = (p.x + bound) * inv2b;
    float ny = (p.y + bound) * inv2b;
    float cx = fminf(fmaxf(nx * (float)RESO - 0.5f, 0.0f), (float)(RESO - 1));
    float cy = fminf(fmaxf(ny * (float)RESO - 0.5f, 0.0f), (float)(RESO - 1));
    float cx0 = floorf(cx), cy0 = floorf(cy);
    float cx1 = fminf(cx0 + 1.0f, (float)(RESO - 1));
    float cy1 = fminf(cy0 + 1.0f, (float)(RESO - 1));
    float u = cx - cx0, v = cy - cy0;

    // Blended hidden activations: H[j2] holds (h_{2j2}, h_{2j2+1}) accumulated
    // over the 4 outer corners with their bilinear weights (valid since
    // layer 2 is linear: sum_c cw_c * W1 * relu(W0 f_c) = W1 * sum_c cw_c*relu(...)).
    u64 H[32];
    #pragma unroll
    for (int j2 = 0; j2 < 32; j2++) H[j2] = 0ull;

    #pragma unroll 1
    for (int cc = 0; cc < 4; cc++) {
        int bx = cc & 1, by = cc >> 1;
        float a  = bx ? cx1 : cx0;
        float bb = by ? cy1 : cy0;
        float cw = (bx ? u : 1.0f - u) * (by ? v : 1.0f - v);

        float gx = (a  + 0.5f) * (1.0f / (float)RESO);
        float gy = (bb + 0.5f) * (1.0f / (float)RESO);

        u64 F[NLEV];   // packed (f_{2l}, f_{2l+1}) per level

        #pragma unroll
        for (int l = 0; l < NLEV; l++) {
            float    scale  = L.scale[l];
            unsigned res    = L.res[l];
            unsigned size   = L.size[l];
            unsigned off    = L.offset[l];
            bool     hashed = (L.hashed[l] != 0);

            float px = fmaf(gx, scale, 0.5f);
            float py = fmaf(gy, scale, 0.5f);
            float fx = floorf(px), fy = floorf(py);
            float frx = px - fx, fry = py - fy;
            unsigned ix = (unsigned)fx, iy = (unsigned)fy;
            float wx0 = 1.0f - frx, wy0 = 1.0f - fry;

            float accx = 0.0f, accy = 0.0f;
            #pragma unroll
            for (int d = 0; d < 4; d++) {
                unsigned gxx = ix + (unsigned)(d & 1);
                unsigned gyy = iy + (unsigned)(d >> 1);
                unsigned idx;
                if (hashed) {
                    idx = (gxx ^ (gyy * PRIME_Y)) & (size - 1u);
                } else {
                    idx = gxx + gyy * res;
                    if (idx >= size) idx -= size;
                }
                float w = ((d & 1) ? frx : wx0) * ((d >> 1) ? fry : wy0);
                float2 t = __ldg(&table[off + idx]);
                accx = fmaf(w, t.x, accx);
                accy = fmaf(w, t.y, accy);
            }
            F[l] = pk2(accx, accy);
        }

        // Layer 1: h_j = relu(w0_j . f) * cw, accumulated into H.
        // Weights come from the constant port (uniform index -> LDC/LDCU),
        // completely off the l1tex data path.
        #pragma unroll
        for (int j2 = 0; j2 < 32; j2++) {
            const u64* w0a = (const u64*)&cW0[(2 * j2)     * 32];
            const u64* w0b = (const u64*)&cW0[(2 * j2 + 1) * 32];
            u64 sa0 = 0ull, sb0 = 0ull, sa1 = 0ull, sb1 = 0ull;
            #pragma unroll
            for (int i = 0; i < 8; i++) {
                sa0 = ffma2(F[2 * i],     w0a[2 * i],     sa0);
                sb0 = ffma2(F[2 * i + 1], w0a[2 * i + 1], sb0);
                sa1 = ffma2(F[2 * i],     w0b[2 * i],     sa1);
                sb1 = ffma2(F[2 * i + 1], w0b[2 * i + 1], sb1);
            }
            float2 v0 = upk2(add2(sa0, sb0));
            float2 v1 = upk2(add2(sa1, sb1));
            float s0 = fmaxf(v0.x + v0.y, 0.0f) * cw;
            float s1 = fmaxf(v1.x + v1.y, 0.0f) * cw;
            H[j2] = add2(H[j2], pk2(s0, s1));
        }
    }

    // Layer 2 (once): out_k = w1_k . hblend. w1 row-major gives contiguous
    // packed pairs matching H's packing.
    float ov[8];
    #pragma unroll
    for (int k = 0; k < 8; k++) {
        const u64* w1r = (const u64*)&cW1[k * 64];
        u64 acc = 0ull;
        #pragma unroll
        for (int j2 = 0; j2 < 32; j2++)
            acc = ffma2(H[j2], w1r[j2], acc);
        float2 aa = upk2(acc);
        ov[k] = aa.x + aa.y;
    }

    float4* op = (float4*)(out + (size_t)n * 8);
    op[0] = make_float4(ov[0], ov[1], ov[2], ov[3]);
    op[1] = make_float4(ov[4], ov[5], ov[6], ov[7]);
}

extern "C" void kernel_launch(void* const* d_in, const int* in_sizes, int n_in,
                              void* d_out, int out_size)
{
    const float2* xy    = (const float2*)d_in[0];
    const float2* table = (const float2*)d_in[1];
    const float*  w0    = (const float*)d_in[2];
    const float*  w1    = (const float*)d_in[3];
    const unsigned* bound = (n_in > 4) ? (const unsigned*)d_in[4] : nullptr;
    int bound_elems = (n_in > 4) ? in_sizes[4] : 0;

    int N = in_sizes[0] / 2;

    // Weights -> constant memory (device-to-device async copy; graph-capturable,
    // no allocation).
    cudaMemcpyToSymbolAsync(cW0, w0, 64 * 32 * sizeof(float), 0,
                            cudaMemcpyDeviceToDevice, 0);
    cudaMemcpyToSymbolAsync(cW1, w1, 8 * 64 * sizeof(float), 0,
                            cudaMemcpyDeviceToDevice, 0);

    // Level constants — same double-precision libm sequence as the numpy
    // reference so ceil() boundaries match exactly.
    Levels L;
    double b = exp2(log2(2048.0 / 16.0) / 15.0);
    unsigned off = 0;
    for (int l = 0; l < NLEV; l++) {
        double s = 16.0 * pow(b, (double)l) - 1.0;
        int r = (int)ceil(s) + 1;
        unsigned long long pp = (unsigned long long)r * (unsigned long long)r;
        unsigned psz = (pp > (unsigned long long)(1u << 19)) ? (1u << 19) : (unsigned)pp;
        psz = (psz + 7u) / 8u * 8u;
        L.scale[l]  = (float)s;
        L.res[l]    = (unsigned)r;
        L.size[l]   = psz;
        L.offset[l] = off;
        L.hashed[l] = (pp > (unsigned long long)psz) ? 1u : 0u;
        off += psz;
    }

    int threads = 128;
    int blocks = (N + threads - 1) / threads;
    plane_kernel<<<blocks, threads>>>(xy, table, bound, bound_elems,
                                      (float*)d_out, N, L);
}

// round 3
// speedup vs baseline: 1.5238x; 1.3567x over previous
#include <cuda_runtime.h>
#include <math.h>

#define NLEV 16
#define RESO 2048
#define PRIME_Y 2654435761u

struct Levels {
    float    scale[NLEV];
    unsigned res[NLEV];
    unsigned size[NLEV];
    unsigned offset[NLEV];
    unsigned hashed[NLEV];
};

typedef unsigned long long u64;

__constant__ float cW0[64 * 32];   // full W0; kernel reads rows 0..31 from here
__constant__ float cW1[8 * 64];

__device__ __forceinline__ u64 pk2(float lo, float hi) {
    u64 r; asm("mov.b64 %0,{%1,%2};" : "=l"(r) : "f"(lo), "f"(hi)); return r;
}
__device__ __forceinline__ float2 upk2(u64 a) {
    float2 f; asm("mov.b64 {%0,%1},%2;" : "=f"(f.x), "=f"(f.y) : "l"(a)); return f;
}
__device__ __forceinline__ u64 ffma2(u64 a, u64 b, u64 c) {
    u64 d; asm("fma.rn.f32x2 %0,%1,%2,%3;" : "=l"(d) : "l"(a), "l"(b), "l"(c)); return d;
}
__device__ __forceinline__ u64 add2(u64 a, u64 b) {
    u64 d; asm("add.rn.f32x2 %0,%1,%2;" : "=l"(d) : "l"(a), "l"(b)); return d;
}

__device__ __forceinline__ float decode_bound(const unsigned* p, int elems) {
    if (!p || elems <= 0) return 1.0f;
    unsigned a = p[0];
    float ff = __uint_as_float(a);
    if (isfinite(ff) && fabsf(ff) > 1e-6f && fabsf(ff) < 1e9f) return ff;
    int ai = (int)a;
    if (ai != 0 && ai > -1000000000 && ai < 1000000000) return (float)ai;
    if (elems >= 2) {
        double d = __hiloint2double((int)p[1], (int)a);
        if (isfinite(d) && fabs(d) > 1e-6 && fabs(d) < 1e9) return (float)d;
    }
    return 1.0f;
}

__global__ __launch_bounds__(128)
void plane_kernel(const float2* __restrict__ xy,
                  const float2* __restrict__ table,
                  const float*  __restrict__ w0g,
                  const unsigned* __restrict__ bound_raw,
                  int bound_elems,
                  float* __restrict__ out,
                  int N, Levels L)
{
    // W0 rows 32..63 staged in shared: weight traffic split across the
    // constant port (LDC.128, rows 0..31) and the smem port (LDS.128).
    __shared__ float sW0hi[32 * 32];
    for (int i = threadIdx.x; i < 32 * 32; i += 128) sW0hi[i] = w0g[32 * 32 + i];
    __syncthreads();

    int n = blockIdx.x * blockDim.x + threadIdx.x;
    if (n >= N) return;

    float bound = decode_bound(bound_raw, bound_elems);

    float2 p = xy[n];
    float inv2b = 0.5f / bound;
    float nx = (p.x + bound) * inv2b;
    float ny = (p.y + bound) * inv2b;
    float cx = fminf(fmaxf(nx * (float)RESO - 0.5f, 0.0f), (float)(RESO - 1));
    float cy = fminf(fmaxf(ny * (float)RESO - 0.5f, 0.0f), (float)(RESO - 1));
    float cx0 = floorf(cx), cy0 = floorf(cy);
    float cx1 = fminf(cx0 + 1.0f, (float)(RESO - 1));
    float cy1 = fminf(cy0 + 1.0f, (float)(RESO - 1));
    float u = cx - cx0, v = cy - cy0;

    float gx0 = (cx0 + 0.5f) * (1.0f / (float)RESO);
    float gx1 = (cx1 + 0.5f) * (1.0f / (float)RESO);
    float gyA = (cy0 + 0.5f) * (1.0f / (float)RESO);
    float gyB = (cy1 + 0.5f) * (1.0f / (float)RESO);

    u64 H[32];
    #pragma unroll
    for (int j2 = 0; j2 < 32; j2++) H[j2] = 0ull;

    // Two passes, each handling the two corners that share a y coordinate.
    #pragma unroll 1
    for (int pass = 0; pass < 2; pass++) {
        float gy  = pass ? gyB : gyA;
        float vy  = pass ? v : (1.0f - v);
        float cwa = vy * (1.0f - u);   // corner (cx0, cy)
        float cwb = vy * u;            // corner (cx1, cy)

        u64 Fa[NLEV], Fb[NLEV];

        #pragma unroll
        for (int l = 0; l < NLEV; l++) {
            float    scale  = L.scale[l];
            unsigned res    = L.res[l];
            unsigned size   = L.size[l];
            unsigned off    = L.offset[l];
            bool     hashed = (L.hashed[l] != 0);

            // y side shared by both corners in this pass
            float py = fmaf(gy, scale, 0.5f);
            float fy = floorf(py);
            float fry = py - fy;
            unsigned iy = (unsigned)fy;
            float wy0 = 1.0f - fry, wy1 = fry;
            unsigned hy0, hy1;
            if (hashed) { hy0 = iy * PRIME_Y; hy1 = (iy + 1u) * PRIME_Y; }
            else        { hy0 = iy * res;     hy1 = (iy + 1u) * res;     }

            // x side per corner
            float pxa = fmaf(gx0, scale, 0.5f);
            float pxb = fmaf(gx1, scale, 0.5f);
            float fxa = floorf(pxa), fxb = floorf(pxb);
            float fra = pxa - fxa,  frb = pxb - fxb;
            unsigned ixa = (unsigned)fxa, ixb = (unsigned)fxb;

            unsigned i00, i10, i01, i11, j00, j10, j01, j11;
            if (hashed) {
                unsigned m = size - 1u;
                i00 = (ixa        ^ hy0) & m;  i10 = ((ixa + 1u) ^ hy0) & m;
                i01 = (ixa        ^ hy1) & m;  i11 = ((ixa + 1u) ^ hy1) & m;
                j00 = (ixb        ^ hy0) & m;  j10 = ((ixb + 1u) ^ hy0) & m;
                j01 = (ixb        ^ hy1) & m;  j11 = ((ixb + 1u) ^ hy1) & m;
            } else {
                i00 = ixa + hy0;      if (i00 >= size) i00 -= size;
                i10 = ixa + 1u + hy0; if (i10 >= size) i10 -= size;
                i01 = ixa + hy1;      if (i01 >= size) i01 -= size;
                i11 = ixa + 1u + hy1; if (i11 >= size) i11 -= size;
                j00 = ixb + hy0;      if (j00 >= size) j00 -= size;
                j10 = ixb + 1u + hy0; if (j10 >= size) j10 -= size;
                j01 = ixb + hy1;      if (j01 >= size) j01 -= size;
                j11 = ixb + 1u + hy1; if (j11 >= size) j11 -= size;
            }

            float2 ta00 = __ldg(&table[off + i00]);
            float2 ta10 = __ldg(&table[off + i10]);
            float2 ta01 = __ldg(&table[off + i01]);
            float2 ta11 = __ldg(&table[off + i11]);
            float2 tb00 = __ldg(&table[off + j00]);
            float2 tb10 = __ldg(&table[off + j10]);
            float2 tb01 = __ldg(&table[off + j01]);
            float2 tb11 = __ldg(&table[off + j11]);

            float wa0 = 1.0f - fra, wa1 = fra;
            float wb0 = 1.0f - frb, wb1 = frb;
            float a00 = wa0 * wy0, a10 = wa1 * wy0, a01 = wa0 * wy1, a11 = wa1 * wy1;
            float b00 = wb0 * wy0, b10 = wb1 * wy0, b01 = wb0 * wy1, b11 = wb1 * wy1;

            float ax = a00 * ta00.x; ax = fmaf(a10, ta10.x, ax);
            ax = fmaf(a01, ta01.x, ax); ax = fmaf(a11, ta11.x, ax);
            float ay = a00 * ta00.y; ay = fmaf(a10, ta10.y, ay);
            ay = fmaf(a01, ta01.y, ay); ay = fmaf(a11, ta11.y, ay);
            float bx = b00 * tb00.x; bx = fmaf(b10, tb10.x, bx);
            bx = fmaf(b01, tb01.x, bx); bx = fmaf(b11, tb11.x, bx);
            float by = b00 * tb00.y; by = fmaf(b10, tb10.y, by);
            by = fmaf(b01, tb01.y, by); by = fmaf(b11, tb11.y, by);

            Fa[l] = pk2(ax, ay);
            Fb[l] = pk2(bx, by);
        }

        // Layer 1: rows 0..31 from constant port
        #pragma unroll 2
        for (int j2 = 0; j2 < 16; j2++) {
            const ulonglong2* r0 = (const ulonglong2*)&cW0[(2 * j2)     * 32];
            const ulonglong2* r1 = (const ulonglong2*)&cW0[(2 * j2 + 1) * 32];
            u64 a0 = 0ull, b0 = 0ull, a1 = 0ull, b1 = 0ull;
            #pragma unroll
            for (int i = 0; i < 8; i++) {
                ulonglong2 wp0 = r0[i], wp1 = r1[i];
                a0 = ffma2(Fa[2 * i], wp0.x, a0); a0 = ffma2(Fa[2 * i + 1], wp0.y, a0);
                b0 = ffma2(Fb[2 * i], wp0.x, b0); b0 = ffma2(Fb[2 * i + 1], wp0.y, b0);
                a1 = ffma2(Fa[2 * i], wp1.x, a1); a1 = ffma2(Fa[2 * i + 1], wp1.y, a1);
                b1 = ffma2(Fb[2 * i], wp1.x, b1); b1 = ffma2(Fb[2 * i + 1], wp1.y, b1);
            }
            float2 va0 = upk2(a0), vb0 = upk2(b0), va1 = upk2(a1), vb1 = upk2(b1);
            float h0 = fmaf(fmaxf(vb0.x + vb0.y, 0.0f), cwb,
                            fmaxf(va0.x + va0.y, 0.0f) * cwa);
            float h1 = fmaf(fmaxf(vb1.x + vb1.y, 0.0f), cwb,
                            fmaxf(va1.x + va1.y, 0.0f) * cwa);
            H[j2] = add2(H[j2], pk2(h0, h1));
        }

        // Layer 1: rows 32..63 from shared port
        #pragma unroll 2
        for (int j2 = 16; j2 < 32; j2++) {
            const ulonglong2* r0 = (const ulonglong2*)&sW0hi[(2 * j2 - 32) * 32];
            const ulonglong2* r1 = (const ulonglong2*)&sW0hi[(2 * j2 - 31) * 32];
            u64 a0 = 0ull, b0 = 0ull, a1 = 0ull, b1 = 0ull;
            #pragma unroll
            for (int i = 0; i < 8; i++) {
                ulonglong2 wp0 = r0[i], wp1 = r1[i];
                a0 = ffma2(Fa[2 * i], wp0.x, a0); a0 = ffma2(Fa[2 * i + 1], wp0.y, a0);
                b0 = ffma2(Fb[2 * i], wp0.x, b0); b0 = ffma2(Fb[2 * i + 1], wp0.y, b0);
                a1 = ffma2(Fa[2 * i], wp1.x, a1); a1 = ffma2(Fa[2 * i + 1], wp1.y, a1);
                b1 = ffma2(Fb[2 * i], wp1.x, b1); b1 = ffma2(Fb[2 * i + 1], wp1.y, b1);
            }
            float2 va0 = upk2(a0), vb0 = upk2(b0), va1 = upk2(a1), vb1 = upk2(b1);
            float h0 = fmaf(fmaxf(vb0.x + vb0.y, 0.0f), cwb,
                            fmaxf(va0.x + va0.y, 0.0f) * cwa);
            float h1 = fmaf(fmaxf(vb1.x + vb1.y, 0.0f), cwb,
                            fmaxf(va1.x + va1.y, 0.0f) * cwa);
            H[j2] = add2(H[j2], pk2(h0, h1));
        }
    }

    // Layer 2 once on the blended hidden vector (constant port)
    float ov[8];
    #pragma unroll
    for (int k = 0; k < 8; k++) {
        const u64* w1r = (const u64*)&cW1[k * 64];
        u64 acc0 = 0ull, acc1 = 0ull;
        #pragma unroll
        for (int j2 = 0; j2 < 32; j2 += 2) {
            acc0 = ffma2(H[j2],     w1r[j2],     acc0);
            acc1 = ffma2(H[j2 + 1], w1r[j2 + 1], acc1);
        }
        float2 aa = upk2(add2(acc0, acc1));
        ov[k] = aa.x + aa.y;
    }

    float4* op = (float4*)(out + (size_t)n * 8);
    op[0] = make_float4(ov[0], ov[1], ov[2], ov[3]);
    op[1] = make_float4(ov[4], ov[5], ov[6], ov[7]);
}

extern "C" void kernel_launch(void* const* d_in, const int* in_sizes, int n_in,
                              void* d_out, int out_size)
{
    const float2* xy    = (const float2*)d_in[0];
    const float2* table = (const float2*)d_in[1];
    const float*  w0    = (const float*)d_in[2];
    const float*  w1    = (const float*)d_in[3];
    const unsigned* bound = (n_in > 4) ? (const unsigned*)d_in[4] : nullptr;
    int bound_elems = (n_in > 4) ? in_sizes[4] : 0;

    int N = in_sizes[0] / 2;

    cudaMemcpyToSymbolAsync(cW0, w0, 64 * 32 * sizeof(float), 0,
                            cudaMemcpyDeviceToDevice, 0);
    cudaMemcpyToSymbolAsync(cW1, w1, 8 * 64 * sizeof(float), 0,
                            cudaMemcpyDeviceToDevice, 0);

    // Level constants — same double-precision libm sequence as the numpy
    // reference so ceil() boundaries match exactly.
    Levels L;
    double b = exp2(log2(2048.0 / 16.0) / 15.0);
    unsigned off = 0;
    for (int l = 0; l < NLEV; l++) {
        double s = 16.0 * pow(b, (double)l) - 1.0;
        int r = (int)ceil(s) + 1;
        unsigned long long pp = (unsigned long long)r * (unsigned long long)r;
        unsigned psz = (pp > (unsigned long long)(1u << 19)) ? (1u << 19) : (unsigned)pp;
        psz = (psz + 7u) / 8u * 8u;
        L.scale[l]  = (float)s;
        L.res[l]    = (unsigned)r;
        L.size[l]   = psz;
        L.offset[l] = off;
        L.hashed[l] = (pp > (unsigned long long)psz) ? 1u : 0u;
        off += psz;
    }

    int threads = 128;
    int blocks = (N + threads - 1) / threads;
    plane_kernel<<<blocks, threads>>>(xy, table, w0, bound, bound_elems,
                                      (float*)d_out, N, L);
}

// round 4
// speedup vs baseline: 2.6271x; 1.7241x over previous
#include <cuda_runtime.h>
#include <math.h>

#define NLEV 16
#define RESO 2048
#define PRIME_Y 2654435761u

struct Levels {
    float    scale[NLEV];
    unsigned res[NLEV];
    unsigned size[NLEV];
    unsigned offset[NLEV];
    unsigned hashed[NLEV];
};

typedef unsigned long long u64;

__constant__ float cW0[64 * 32];   // [j][i] row-major
__constant__ float cW1t[64 * 8];   // transposed: [j][k]
__device__   float g_w1t[64 * 8];  // staging for the transpose

__device__ __forceinline__ u64 pk2(float lo, float hi) {
    u64 r; asm("mov.b64 %0,{%1,%2};" : "=l"(r) : "f"(lo), "f"(hi)); return r;
}
__device__ __forceinline__ float2 upk2(u64 a) {
    float2 f; asm("mov.b64 {%0,%1},%2;" : "=f"(f.x), "=f"(f.y) : "l"(a)); return f;
}
__device__ __forceinline__ u64 ffma2(u64 a, u64 b, u64 c) {
    u64 d; asm("fma.rn.f32x2 %0,%1,%2,%3;" : "=l"(d) : "l"(a), "l"(b), "l"(c)); return d;
}
__device__ __forceinline__ u64 mul2(u64 a, u64 b) {
    u64 d; asm("mul.rn.f32x2 %0,%1,%2;" : "=l"(d) : "l"(a), "l"(b)); return d;
}

__device__ __forceinline__ float decode_bound(const unsigned* p, int elems) {
    if (!p || elems <= 0) return 1.0f;
    unsigned a = p[0];
    float ff = __uint_as_float(a);
    if (isfinite(ff) && fabsf(ff) > 1e-6f && fabsf(ff) < 1e9f) return ff;
    int ai = (int)a;
    if (ai != 0 && ai > -1000000000 && ai < 1000000000) return (float)ai;
    if (elems >= 2) {
        double d = __hiloint2double((int)p[1], (int)a);
        if (isfinite(d) && fabs(d) > 1e-6 && fabs(d) < 1e9) return (float)d;
    }
    return 1.0f;
}

__global__ void transpose_w1(const float* __restrict__ w1) {
    int i = threadIdx.x;             // 512 threads
    int k = i >> 6, j = i & 63;
    g_w1t[j * 8 + k] = w1[i];
}

__global__ __launch_bounds__(128)
void plane_kernel(const float2* __restrict__ xy,
                  const float2* __restrict__ table,
                  const unsigned* __restrict__ bound_raw,
                  int bound_elems,
                  float* __restrict__ out,
                  int N, Levels L)
{
    int n = blockIdx.x * blockDim.x + threadIdx.x;
    if (n >= N) return;

    float bound = decode_bound(bound_raw, bound_elems);

    float2 p = xy[n];
    float inv2b = 0.5f / bound;
    float nxv = (p.x + bound) * inv2b;
    float nyv = (p.y + bound) * inv2b;
    float cx = fminf(fmaxf(nxv * (float)RESO - 0.5f, 0.0f), (float)(RESO - 1));
    float cy = fminf(fmaxf(nyv * (float)RESO - 0.5f, 0.0f), (float)(RESO - 1));
    float cx0 = floorf(cx), cy0 = floorf(cy);
    float cx1 = fminf(cx0 + 1.0f, (float)(RESO - 1));
    float cy1 = fminf(cy0 + 1.0f, (float)(RESO - 1));
    float u = cx - cx0, v = cy - cy0;

    float gx0 = (cx0 + 0.5f) * (1.0f / (float)RESO);
    float gx1 = (cx1 + 0.5f) * (1.0f / (float)RESO);
    float gyA = (cy0 + 0.5f) * (1.0f / (float)RESO);
    float gyB = (cy1 + 0.5f) * (1.0f / (float)RESO);

    // Features for all 4 outer corners, channel-pair packed per level.
    // a=(x0,y0) b=(x1,y0) c=(x0,y1) d=(x1,y1)
    u64 Fa[NLEV], Fb[NLEV], Fc[NLEV], Fd[NLEV];

    #pragma unroll
    for (int l = 0; l < NLEV; l++) {
        float    scale  = L.scale[l];
        unsigned res    = L.res[l];
        unsigned size   = L.size[l];
        unsigned off    = L.offset[l];
        bool     hashed = (L.hashed[l] != 0);

        float pxa = fmaf(gx0, scale, 0.5f);
        float pxb = fmaf(gx1, scale, 0.5f);
        float pya = fmaf(gyA, scale, 0.5f);
        float pyb = fmaf(gyB, scale, 0.5f);
        float fxa = floorf(pxa), fxb = floorf(pxb);
        float fya = floorf(pya), fyb = floorf(pyb);
        float ua1 = pxa - fxa, ua0 = 1.0f - ua1;
        float ub1 = pxb - fxb, ub0 = 1.0f - ub1;
        float va1 = pya - fya, va0 = 1.0f - va1;
        float vb1 = pyb - fyb, vb0 = 1.0f - vb1;
        unsigned ix = (unsigned)fxa, iy = (unsigned)fya;
        bool bdx = fxb > fxa;     // corners straddle a cell in x
        bool bdy = fyb > fya;

        // 3x3 union of the 4 corners' bilinear taps
        unsigned i00, i01, i02, i10, i11, i12, i20, i21, i22;
        if (hashed) {
            unsigned m = size - 1u;
            unsigned hy0 = iy * PRIME_Y, hy1 = hy0 + PRIME_Y, hy2 = hy1 + PRIME_Y;
            i00 = (ix ^ hy0) & m; i01 = ((ix + 1u) ^ hy0) & m; i02 = ((ix + 2u) ^ hy0) & m;
            i10 = (ix ^ hy1) & m; i11 = ((ix + 1u) ^ hy1) & m; i12 = ((ix + 2u) ^ hy1) & m;
            i20 = (ix ^ hy2) & m; i21 = ((ix + 1u) ^ hy2) & m; i22 = ((ix + 2u) ^ hy2) & m;
        } else {
            // max index is (res+1)^2 < 2*size, so one conditional subtract wraps
            unsigned hy0 = iy * res, hy1 = hy0 + res, hy2 = hy1 + res;
            i00 = ix + hy0;      if (i00 >= size) i00 -= size;
            i01 = ix + 1u + hy0; if (i01 >= size) i01 -= size;
            i02 = ix + 2u + hy0; if (i02 >= size) i02 -= size;
            i10 = ix + hy1;      if (i10 >= size) i10 -= size;
            i11 = ix + 1u + hy1; if (i11 >= size) i11 -= size;
            i12 = ix + 2u + hy1; if (i12 >= size) i12 -= size;
            i20 = ix + hy2;      if (i20 >= size) i20 -= size;
            i21 = ix + 1u + hy2; if (i21 >= size) i21 -= size;
            i22 = ix + 2u + hy2; if (i22 >= size) i22 -= size;
        }

        const u64* tb = (const u64*)(table + off);
        u64 T00 = __ldg(tb + i00);
        u64 T01 = __ldg(tb + i01);
        u64 T10 = __ldg(tb + i10);
        u64 T11 = __ldg(tb + i11);
        u64 T02 = 0ull, T12 = 0ull, T20 = 0ull, T21 = 0ull, T22 = 0ull;
        if (bdx) { T02 = __ldg(tb + i02); T12 = __ldg(tb + i12); }
        if (bdy) { T20 = __ldg(tb + i20); T21 = __ldg(tb + i21); }
        if (bdx && bdy) { T22 = __ldg(tb + i22); }

        u64 ua0p = pk2(ua0, ua0), ua1p = pk2(ua1, ua1);
        u64 ub0p = pk2(ub0, ub0), ub1p = pk2(ub1, ub1);
        u64 va0p = pk2(va0, va0), va1p = pk2(va1, va1);
        u64 vb0p = pk2(vb0, vb0), vb1p = pk2(vb1, vb1);

        // x-reduction for x-corner 0 (cols 0,1) on all 3 rows
        u64 S00 = ffma2(ua1p, T01, mul2(ua0p, T00));
        u64 S01 = ffma2(ua1p, T11, mul2(ua0p, T10));
        u64 S02 = ffma2(ua1p, T21, mul2(ua0p, T20));
        // x-reduction for x-corner 1 (cols bdx, bdx+1)
        u64 X0r0 = bdx ? T01 : T00, X1r0 = bdx ? T02 : T01;
        u64 X0r1 = bdx ? T11 : T10, X1r1 = bdx ? T12 : T11;
        u64 X0r2 = bdx ? T21 : T20, X1r2 = bdx ? T22 : T21;
        u64 S10 = ffma2(ub1p, X1r0, mul2(ub0p, X0r0));
        u64 S11 = ffma2(ub1p, X1r1, mul2(ub0p, X0r1));
        u64 S12 = ffma2(ub1p, X1r2, mul2(ub0p, X0r2));
        // y-reduction
        Fa[l] = ffma2(va1p, S01, mul2(va0p, S00));
        Fb[l] = ffma2(va1p, S11, mul2(va0p, S10));
        u64 Y0a = bdy ? S01 : S00, Y1a = bdy ? S02 : S01;
        u64 Y0b = bdy ? S11 : S10, Y1b = bdy ? S12 : S11;
        Fc[l] = ffma2(vb1p, Y1a, mul2(vb0p, Y0a));
        Fd[l] = ffma2(vb1p, Y1b, mul2(vb0p, Y0b));
    }

    float cwa = (1.0f - u) * (1.0f - v);
    float cwb = u * (1.0f - v);
    float cwc = (1.0f - u) * v;
    float cwd = u * v;

    // Fused MLP: layer1 (per-corner relu, bilinear blend) folded straight into
    // layer2 accumulators. All weights from the constant port.
    u64 O0 = 0ull, O1 = 0ull, O2 = 0ull, O3 = 0ull;
    #pragma unroll 1
    for (int j2 = 0; j2 < 32; j2++) {
        const ulonglong2* r0 = (const ulonglong2*)&cW0[(2 * j2) * 32];
        const ulonglong2* r1 = (const ulonglong2*)&cW0[(2 * j2 + 1) * 32];
        u64 a0 = 0ull, b0 = 0ull, c0 = 0ull, d0 = 0ull;
        u64 a1 = 0ull, b1 = 0ull, c1 = 0ull, d1 = 0ull;
        #pragma unroll
        for (int i = 0; i < 8; i++) {
            ulonglong2 w_0 = r0[i], w_1 = r1[i];
            a0 = ffma2(Fa[2 * i], w_0.x, a0); a0 = ffma2(Fa[2 * i + 1], w_0.y, a0);
            b0 = ffma2(Fb[2 * i], w_0.x, b0); b0 = ffma2(Fb[2 * i + 1], w_0.y, b0);
            c0 = ffma2(Fc[2 * i], w_0.x, c0); c0 = ffma2(Fc[2 * i + 1], w_0.y, c0);
            d0 = ffma2(Fd[2 * i], w_0.x, d0); d0 = ffma2(Fd[2 * i + 1], w_0.y, d0);
            a1 = ffma2(Fa[2 * i], w_1.x, a1); a1 = ffma2(Fa[2 * i + 1], w_1.y, a1);
            b1 = ffma2(Fb[2 * i], w_1.x, b1); b1 = ffma2(Fb[2 * i + 1], w_1.y, b1);
            c1 = ffma2(Fc[2 * i], w_1.x, c1); c1 = ffma2(Fc[2 * i + 1], w_1.y, c1);
            d1 = ffma2(Fd[2 * i], w_1.x, d1); d1 = ffma2(Fd[2 * i + 1], w_1.y, d1);
        }
        float2 A0 = upk2(a0), B0 = upk2(b0), C0 = upk2(c0), D0 = upk2(d0);
        float2 A1 = upk2(a1), B1 = upk2(b1), C1 = upk2(c1), D1 = upk2(d1);
        float h0 = fmaxf(A0.x + A0.y, 0.0f) * cwa;
        h0 = fmaf(fmaxf(B0.x + B0.y, 0.0f), cwb, h0);
        h0 = fmaf(fmaxf(C0.x + C0.y, 0.0f), cwc, h0);
        h0 = fmaf(fmaxf(D0.x + D0.y, 0.0f), cwd, h0);
        float h1 = fmaxf(A1.x + A1.y, 0.0f) * cwa;
        h1 = fmaf(fmaxf(B1.x + B1.y, 0.0f), cwb, h1);
        h1 = fmaf(fmaxf(C1.x + C1.y, 0.0f), cwc, h1);
        h1 = fmaf(fmaxf(D1.x + D1.y, 0.0f), cwd, h1);

        const ulonglong2* wt = (const ulonglong2*)&cW1t[(2 * j2) * 8];
        ulonglong2 q0 = wt[0], q1 = wt[1];   // row 2j2:   k 0..3, 4..7
        ulonglong2 q2 = wt[2], q3 = wt[3];   // row 2j2+1
        u64 t0 = pk2(h0, h0), t1 = pk2(h1, h1);
        O0 = ffma2(t0, q0.x, O0); O1 = ffma2(t0, q0.y, O1);
        O2 = ffma2(t0, q1.x, O2); O3 = ffma2(t0, q1.y, O3);
        O0 = ffma2(t1, q2.x, O0); O1 = ffma2(t1, q2.y, O1);
        O2 = ffma2(t1, q3.x, O2); O3 = ffma2(t1, q3.y, O3);
    }

    float2 r0 = upk2(O0), r1 = upk2(O1), r2 = upk2(O2), r3 = upk2(O3);
    float4* op = (float4*)(out + (size_t)n * 8);
    op[0] = make_float4(r0.x, r0.y, r1.x, r1.y);
    op[1] = make_float4(r2.x, r2.y, r3.x, r3.y);
}

extern "C" void kernel_launch(void* const* d_in, const int* in_sizes, int n_in,
                              void* d_out, int out_size)
{
    const float2* xy    = (const float2*)d_in[0];
    const float2* table = (const float2*)d_in[1];
    const float*  w0    = (const float*)d_in[2];
    const float*  w1    = (const float*)d_in[3];
    const unsigned* bound = (n_in > 4) ? (const unsigned*)d_in[4] : nullptr;
    int bound_elems = (n_in > 4) ? in_sizes[4] : 0;

    int N = in_sizes[0] / 2;

    cudaMemcpyToSymbolAsync(cW0, w0, 64 * 32 * sizeof(float), 0,
                            cudaMemcpyDeviceToDevice, 0);
    // Transpose w1 on device, then stage into constant memory.
    transpose_w1<<<1, 512>>>(w1);
    void* w1t_ptr = nullptr;
    cudaGetSymbolAddress(&w1t_ptr, g_w1t);
    cudaMemcpyToSymbolAsync(cW1t, w1t_ptr, 64 * 8 * sizeof(float), 0,
                            cudaMemcpyDeviceToDevice, 0);

    // Level constants — same double-precision libm sequence as the numpy
    // reference so ceil() boundaries match exactly.
    Levels L;
    double b = exp2(log2(2048.0 / 16.0) / 15.0);
    unsigned off = 0;
    for (int l = 0; l < NLEV; l++) {
        double s = 16.0 * pow(b, (double)l) - 1.0;
        int r = (int)ceil(s) + 1;
        unsigned long long pp = (unsigned long long)r * (unsigned long long)r;
        unsigned psz = (pp > (unsigned long long)(1u << 19)) ? (1u << 19) : (unsigned)pp;
        psz = (psz + 7u) / 8u * 8u;
        L.scale[l]  = (float)s;
        L.res[l]    = (unsigned)r;
        L.size[l]   = psz;
        L.offset[l] = off;
        L.hashed[l] = (pp > (unsigned long long)psz) ? 1u : 0u;
        off += psz;
    }

    int threads = 128;
    int blocks = (N + threads - 1) / threads;
    plane_kernel<<<blocks, threads>>>(xy, table, bound, bound_elems,
                                      (float*)d_out, N, L);
}